// round 14
// baseline (speedup 1.0000x reference)
#include <cuda_runtime.h>
#include <math.h>

#define VOCABN 30000
#define DN 100
#define RN 150
#define RWN 50
#define SN 50
#define CN 20
#define BN 256
#define LN 512
#define VR 4                      // vocab rows per k1-role block (R8-proven)
#define K1BLOCKS (VOCABN / VR)    // 7500
#define K0BLOCKS 32
#define WIN 68                    // k2 shared window stride
#define PHW 200                   // per-(b,l) row: p[0:150] | h[150:200]

typedef unsigned long long ull;

// ---- folded constants / tables / deferred-score buffer (static device) ----
__device__ float g_Tv[VOCABN * RN];    // blended V embedding per vocab id
__device__ float g_Trw[VOCABN * SN];   // (Tv*Cvs)@Wrs1 + bs1 per vocab id
__device__ float g_wild[SN * SN];      // [s][t]
__device__ float g_S2cT[RN * SN];      // S2[t][r]*Cvs[r], stored [r][t]
__device__ float g_SCf[PHW * CN];      // [k][c] score matrix (prio_a folded)
__device__ float g_PH[(size_t)BN * LN * PHW];  // p|h per (b,l)  (~105 MB)

// ---- packed f32x2 helpers ----
__device__ __forceinline__ ull FMA2(ull a, ull b, ull c) {
    ull d;
    asm("fma.rn.f32x2 %0, %1, %2, %3;" : "=l"(d) : "l"(a), "l"(b), "l"(c));
    return d;
}
__device__ __forceinline__ ull ADD2(ull a, ull b) {
    ull d;
    asm("add.rn.f32x2 %0, %1, %2;" : "=l"(d) : "l"(a), "l"(b));
    return d;
}
__device__ __forceinline__ ull PACK2(float a, float b) {
    union { ull u; float2 f; } x;
    x.f = make_float2(a, b);
    return x.u;
}
__device__ __forceinline__ float2 UNPK(ull a) {
    union { ull u; float2 f; } x;
    x.u = a;
    return x.f;
}
__device__ __forceinline__ float SIG(float v) {
    return 1.f / (1.f + __expf(-v));
}

// Shuffle-broadcast 50-dot, G=2 (outputs packed in the f32x2 lanes).
// Warp loads the activation window COALESCED (2 LDS.32 = 2 wavefronts),
// then per k: 1 SHFL (MIO) + pair-dup (ALU) + 1 FMA2 (FMA) — three pipes,
// zero crossbar broadcast traffic. w[k] = (w_out0[k], w_out1[k]).
__device__ __forceinline__ ull dot50_shfl(const float* __restrict__ a,
                                          int lane,
                                          const ull* __restrict__ w) {
    float ha0 = a[lane];
    float ha1 = a[32 + lane];   // only lanes 0..17 are ever shuffled from
    ull c0 = 0, c1 = 0, c2 = 0, c3 = 0;
#pragma unroll
    for (int k = 0; k < 50; k++) {
        float hk = __shfl_sync(0xffffffffu, (k < 32) ? ha0 : ha1, k & 31);
        ull hp = PACK2(hk, hk);
        if ((k & 3) == 0)      c0 = FMA2(w[k], hp, c0);
        else if ((k & 3) == 1) c1 = FMA2(w[k], hp, c1);
        else if ((k & 3) == 2) c2 = FMA2(w[k], hp, c2);
        else                   c3 = FMA2(w[k], hp, c3);
    }
    return ADD2(ADD2(c0, c1), ADD2(c2, c3));
}

// ---------------------------------------------------------------------------
// k01: merged constant folding (k0 role, 32 blocks, emits g_SCf with prio_a
// folded) + vocab tables (k1 role, 7500 blocks x 4 vocab rows — the R8
// configuration that measured fastest).
// ---------------------------------------------------------------------------
__global__ void __launch_bounds__(160)
k01(const float* __restrict__ C_embed, const float* __restrict__ C_w,
    const float* __restrict__ S1w, const float* __restrict__ S2w,
    const float* __restrict__ WW, const float* __restrict__ hT,
    const float* __restrict__ S2, const float* __restrict__ prio_a,
    const float* __restrict__ W_embed, const float* __restrict__ embed_r,
    const float* __restrict__ V_embed, const float* __restrict__ beta,
    const float* __restrict__ Wrs1, const float* __restrict__ bs1) {
    __shared__ float sm[VR * DN + VR * RN];
    __shared__ float k0sm[2 * RN + 2 * RWN];
    int t = threadIdx.x;

    if (blockIdx.x >= K1BLOCKS) {
        // ---------------- k0 role ----------------
        float* cvs = k0sm;
        float* u   = k0sm + RN;
        float* cw  = k0sm + 2 * RN;
        float* uw  = k0sm + 2 * RN + RWN;
        if (t < RN) {
            float s = 0.f;
#pragma unroll
            for (int c = 0; c < CN; c++) s += C_embed[c * RN + t];
            cvs[t] = s;
            float su = 0.f;
#pragma unroll
            for (int s2 = 0; s2 < SN; s2++) su += hT[s2] * S2[s2 * RN + t];
            u[t] = su;
        }
        if (t < RWN) {
            float s = 0.f;
#pragma unroll
            for (int c = 0; c < CN; c++) s += C_w[c * RWN + t];
            cw[t] = s;
            float su = 0.f;
#pragma unroll
            for (int s2 = 0; s2 < SN; s2++) su += hT[s2] * S2w[s2 * RWN + t];
            uw[t] = su;
        }
        __syncthreads();

        const int N_WLD = SN * SN;      // 2500
        const int N_S2C = RN * SN;      // 7500
        const int N_SCF = PHW * CN;     // 4000
        const int TOT = N_WLD + N_S2C + N_SCF;
        int bid = blockIdx.x - K1BLOCKS;
        int stride = K0BLOCKS * 160;
        for (int g = bid * 160 + t; g < TOT; g += stride) {
            int i = g;
            if (i < N_WLD) {
                int s = i / SN, tt = i % SN;
                float acc = WW[i];
#pragma unroll
                for (int r = 0; r < RWN; r++)
                    acc += S1w[s * RWN + r] * cw[r] * S2w[tt * RWN + r];
                g_wild[i] = acc;
                continue;
            }
            i -= N_WLD;
            if (i < N_S2C) {
                int r = i / SN, tt = i % SN;
                g_S2cT[i] = S2[tt * RN + r] * cvs[r];
                continue;
            }
            i -= N_S2C;
            {
                int k = i / CN, c = i % CN;
                float v;
                if (k < RN) {
                    v = C_embed[c * RN + k] * u[k];
                } else {
                    int s = k - RN;
                    float acc = 0.f;
#pragma unroll
                    for (int r = 0; r < RWN; r++)
                        acc += S1w[s * RWN + r] * uw[r] * C_w[c * RWN + r];
                    v = acc;
                }
                g_SCf[i] = v * prio_a[c];
            }
        }
        return;
    }

    // ---------------- k1 role (VR=4, R8 config) ----------------
    float* w4 = sm;
    float (*q4)[RN] = (float (*)[RN])(sm + VR * DN);
    int v0 = blockIdx.x * VR;

    for (int i = t; i < VR * DN; i += 160)
        w4[i] = W_embed[v0 * DN + i];
    __syncthreads();

    if (t < RN) {
        float cv = 0.f;
#pragma unroll
        for (int c = 0; c < CN; c++) cv += C_embed[c * RN + t];

        float a0 = 0.f, a1 = 0.f, a2 = 0.f, a3 = 0.f;
#pragma unroll 4
        for (int d = 0; d < DN; d++) {
            float e = embed_r[d * RN + t];
            a0 += e * w4[0 * DN + d];
            a1 += e * w4[1 * DN + d];
            a2 += e * w4[2 * DN + d];
            a3 += e * w4[3 * DN + d];
        }
        float b = beta[t];
        float acc[VR] = {a0, a1, a2, a3};
#pragma unroll
        for (int r = 0; r < VR; r++) {
            float th;
            asm("tanh.approx.f32 %0, %1;" : "=f"(th) : "f"(acc[r]));
            float tv = V_embed[(v0 + r) * RN + t] * b + th * (1.f - b);
            g_Tv[(v0 + r) * RN + t] = tv;
            q4[r][t] = tv * cv;
        }
    }
    __syncthreads();

    if (t < SN) {
        float a0 = 0.f, a1 = 0.f, a2 = 0.f, a3 = 0.f;
#pragma unroll 2
        for (int d = 0; d < RN; d++) {
            float wv = Wrs1[d * SN + t];
            a0 += wv * q4[0][d];
            a1 += wv * q4[1][d];
            a2 += wv * q4[2][d];
            a3 += wv * q4[3][d];
        }
        float bb = bs1[t];
        g_Trw[(v0 + 0) * SN + t] = bb + a0;
        g_Trw[(v0 + 1) * SN + t] = bb + a1;
        g_Trw[(v0 + 2) * SN + t] = bb + a2;
        g_Trw[(v0 + 3) * SN + t] = bb + a3;
    }
}

// ---------------------------------------------------------------------------
// k2: sequential recurrence, score-deferred, SHUFFLE-BROADCAST dots.
// 256 CTAs x 256 threads, 1 chain/CTA, 2 CTAs/SM.
//
//   warps 0-3 (t<128): phase-1 over h. t<75: p-pair (outs 2t,2t+1 of S1);
//     t in [75,100): gate pair (Wss1); t>=100: dummy (zero weights, full
//     shuffle participation). Interval B: p-pair store to g_PH + Tv/Trw
//     prefetch for the next token.
//   warps 4-7 (q=warp-4): phase-2, warp-per-CHUNK (chunk is warp-uniform
//     as shuffles require): q<3 -> S2cT chunk over p-window; q=3 -> wild
//     over live h. Lane<25 owns out pair (2*lane, 2*lane+1). Warps 4-6
//     write partial pairs to smem; bar.sync(1,128); warp 7 sums 4 partials,
//     applies gate, writes h (double-buffered). Interval A: h-store to
//     g_PH + next-token preload.
//
// Crossbar traffic/step: ~70 wavefronts (vs ~1664 in the LDS-broadcast
// versions). 2 main barriers + 1 named barrier per step.
// ---------------------------------------------------------------------------
__global__ void __launch_bounds__(256, 2)
k2_recur(const int* __restrict__ tokens,
         const float* __restrict__ S1,
         const float* __restrict__ Wss1,
         const float* __restrict__ h0) {
    __shared__ float act[5 * WIN];
    __shared__ float gz[SN];
    __shared__ __align__(8) ull part[96];
    __shared__ int s_ntok;

    int t = threadIdx.x;
    int lane = t & 31;
    int b = blockIdx.x;
    int tb = b * LN;
    long rb = (long)b * LN;          // PH row base

    ull w[50];
#pragma unroll
    for (int j = 0; j < 50; j++) w[j] = 0ull;

    const bool isP1 = (t < 128);

    // phase-1 role
    int fam = 3;               // 0=p-pair, 1=gate-pair, 3=dummy
    int out0 = 0;
    int p1w = 0;
    // phase-2 role
    int q = 0, o0 = 0;
    bool p2act = false;
    int winOff = 2 * WIN;

    if (isP1) {
        if (t < 75) {
            fam = 0;
            out0 = 2 * t;      // 0..148; pair never straddles a 50-block
            p1w = (2 + out0 / 50) * WIN + (out0 % 50);
#pragma unroll
            for (int k = 0; k < 50; k++)
                w[k] = PACK2(S1[k * RN + out0], S1[k * RN + out0 + 1]);
        } else if (t < 100) {
            fam = 1;
            out0 = 2 * (t - 75);   // 0..48 gate cols
#pragma unroll
            for (int k = 0; k < 50; k++)
                w[k] = PACK2(Wss1[k * SN + out0], Wss1[k * SN + out0 + 1]);
        }
    } else {
        q = (t >> 5) - 4;          // 0..3 chunk per warp
        o0 = 2 * lane;             // out pair for lanes < 25
        p2act = (lane < 25);
        if (q < 3) {
            const float* P = g_S2cT + q * 50 * SN;
            winOff = (2 + q) * WIN;
            if (p2act) {
#pragma unroll
                for (int k = 0; k < 50; k++)
                    w[k] = PACK2(P[k * SN + o0], P[k * SN + o0 + 1]);
            }
        } else {
            if (p2act) {
#pragma unroll
                for (int k = 0; k < 50; k++)
                    w[k] = PACK2(g_wild[k * SN + o0], g_wild[k * SN + o0 + 1]);
            }
        }
    }

    // ---- init: state + prime step-0 gathers ----
    if (t < SN) act[t] = h0[t];
    float2 tvA = make_float2(0.f, 0.f), trA = tvA;
    if (fam == 0) {
        int t0 = tokens[tb];
        tvA = *(const float2*)&g_Tv[t0 * RN + out0];
    } else if (fam == 1) {
        int t0 = tokens[tb];
        trA = *(const float2*)&g_Trw[t0 * SN + out0];
    }
    __syncthreads();

    for (int l = 0; l < LN; l++) {
        int hc = (l & 1) ? WIN : 0;
        float px0 = 0.f, px1 = 0.f;     // p pair kept for the gmem store

        // -------- interval A: phase-1 compute | h-store + token preload -----
        if (isP1) {
            ull r = dot50_shfl(act + hc, lane, w);  // uniform for all lanes
            float2 o = UNPK(r);
            if (fam == 0) {
                px0 = o.x * tvA.x;
                px1 = o.y * tvA.y;
                *(float2*)&act[p1w] = make_float2(px0, px1);
            } else if (fam == 1) {
                *(float2*)&gz[out0] =
                    make_float2(SIG(o.x + trA.x), SIG(o.y + trA.y));
            }
        } else {
            int i = t - 128;
            if (i < 50) {
                g_PH[(rb + l) * PHW + 150 + i] = act[hc + i];
            } else if (t == 239) {
                int nl = (l + 1 < LN) ? l + 1 : l;
                s_ntok = tokens[tb + nl];
            }
        }
        __syncthreads();

        // -------- interval B: phase-2 compute | p-store + prefetch ----------
        if (isP1) {
            if (fam == 0) {
                *(float2*)&g_PH[(rb + l) * PHW + out0] = make_float2(px0, px1);
                tvA = *(const float2*)&g_Tv[s_ntok * RN + out0];
            } else if (fam == 1) {
                trA = *(const float2*)&g_Trw[s_ntok * SN + out0];
            }
        } else {
            int winA = (q == 3) ? hc : winOff;
            ull ps = dot50_shfl(act + winA, lane, w);

            if (q < 3) part[q * 32 + lane] = ps;
            asm volatile("bar.sync 1, 128;" ::: "memory");

            if (q == 3 && p2act) {
                ull s = ADD2(ADD2(part[lane], part[32 + lane]),
                             ADD2(part[64 + lane], ps));
                float2 sv = UNPK(s);
                int hn = WIN - hc;
                float2 hx = *(const float2*)&act[hc + o0];
                float2 z  = *(const float2*)&gz[o0];
                *(float2*)&act[hn + o0] = make_float2(
                    z.x * sv.x + (1.f - z.x) * hx.x,
                    z.y * sv.y + (1.f - z.y) * hx.y);
            }
        }
        __syncthreads();
    }
}

// ---------------------------------------------------------------------------
// k3: deferred scores. out[row][c] = [p|h](row) @ SCf + prio_b.
// 512 blocks x 256 threads, one row per thread; SCf broadcast from shared.
// ---------------------------------------------------------------------------
__global__ void __launch_bounds__(256)
k3_score(const float* __restrict__ prio_b, float* __restrict__ out) {
    __shared__ __align__(16) float sc[PHW * CN];
    int t = threadIdx.x;
    for (int i = t; i < PHW * CN; i += 256) sc[i] = g_SCf[i];
    __syncthreads();

    long row = (long)blockIdx.x * 256 + t;
    const float* ph = g_PH + row * PHW;

    ull acc[10];
#pragma unroll
    for (int c = 0; c < 10; c++) acc[c] = 0ull;

#pragma unroll 4
    for (int k = 0; k < PHW; k += 4) {
        float4 v = *(const float4*)(ph + k);
        const ull* s0 = (const ull*)(sc + (k + 0) * CN);
        const ull* s1 = (const ull*)(sc + (k + 1) * CN);
        const ull* s2 = (const ull*)(sc + (k + 2) * CN);
        const ull* s3 = (const ull*)(sc + (k + 3) * CN);
        ull v0 = PACK2(v.x, v.x), v1 = PACK2(v.y, v.y);
        ull v2 = PACK2(v.z, v.z), v3 = PACK2(v.w, v.w);
#pragma unroll
        for (int c = 0; c < 10; c++) {
            acc[c] = FMA2(s0[c], v0, acc[c]);
            acc[c] = FMA2(s1[c], v1, acc[c]);
            acc[c] = FMA2(s2[c], v2, acc[c]);
            acc[c] = FMA2(s3[c], v3, acc[c]);
        }
    }

    float* o = out + row * CN;
#pragma unroll
    for (int c = 0; c < 10; c++) {
        float2 a = UNPK(acc[c]);
        float2 pb = *(const float2*)(prio_b + 2 * c);
        *(float2*)(o + 2 * c) = make_float2(a.x + pb.x, a.y + pb.y);
    }
}

// ---------------------------------------------------------------------------
// Launch. Inputs (metadata order): tokens, W_embed, embed_r, V_embed,
// C_embed, S1, S2, S1_w, S2_w, C_w, WW, h0, hT, beta_vec, Wss1, Wrs1, bs1,
// prio_a, prio_b
// ---------------------------------------------------------------------------
extern "C" void kernel_launch(void* const* d_in, const int* in_sizes, int n_in,
                              void* d_out, int out_size) {
    const int*   tokens  = (const int*)  d_in[0];
    const float* W_embed = (const float*)d_in[1];
    const float* embed_r = (const float*)d_in[2];
    const float* V_embed = (const float*)d_in[3];
    const float* C_embed = (const float*)d_in[4];
    const float* S1      = (const float*)d_in[5];
    const float* S2      = (const float*)d_in[6];
    const float* S1_w    = (const float*)d_in[7];
    const float* S2_w    = (const float*)d_in[8];
    const float* C_w     = (const float*)d_in[9];
    const float* WW      = (const float*)d_in[10];
    const float* h0      = (const float*)d_in[11];
    const float* hT      = (const float*)d_in[12];
    const float* beta    = (const float*)d_in[13];
    const float* Wss1    = (const float*)d_in[14];
    const float* Wrs1    = (const float*)d_in[15];
    const float* bs1     = (const float*)d_in[16];
    const float* prio_a  = (const float*)d_in[17];
    const float* prio_b  = (const float*)d_in[18];
    float* out = (float*)d_out;

    k01<<<K1BLOCKS + K0BLOCKS, 160>>>(C_embed, C_w, S1_w, S2_w, WW, hT, S2,
                                      prio_a, W_embed, embed_r, V_embed, beta,
                                      Wrs1, bs1);
    k2_recur<<<BN, 256>>>(tokens, S1, Wss1, h0);
    k3_score<<<(BN * LN) / 256, 256>>>(prio_b, out);
}

// round 16
// speedup vs baseline: 1.5038x; 1.5038x over previous
#include <cuda_runtime.h>
#include <math.h>

#define VOCABN 30000
#define DN 100
#define RN 150
#define RWN 50
#define SN 50
#define CN 20
#define BN 256
#define LN 512
#define VR 4                      // vocab rows per k1-role block
#define K1BLOCKS (VOCABN / VR)    // 7500
#define K0BLOCKS 32
#define WIN 68                    // k2 shared window stride
#define PHW 200                   // per-(b,l) row: p[0:150] | h[150:200]

typedef unsigned long long ull;

// ---- folded constants / tables / deferred-score buffer (static device) ----
__device__ float g_Tv[VOCABN * RN];    // blended V embedding per vocab id
__device__ float g_Trw[VOCABN * SN];   // (Tv*Cvs)@Wrs1 + bs1 per vocab id
__device__ float g_wild[SN * SN];      // [s][t]
__device__ float g_S2cT[RN * SN];      // S2[t][r]*Cvs[r], stored [r][t]
__device__ float g_SCf[PHW * CN];      // [k][c] score matrix (prio_a folded)
__device__ float g_PH[(size_t)BN * LN * PHW];  // p|h per (b,l)  (~105 MB)

// ---- packed f32x2 helpers ----
__device__ __forceinline__ ull FMA2(ull a, ull b, ull c) {
    ull d;
    asm("fma.rn.f32x2 %0, %1, %2, %3;" : "=l"(d) : "l"(a), "l"(b), "l"(c));
    return d;
}
__device__ __forceinline__ ull ADD2(ull a, ull b) {
    ull d;
    asm("add.rn.f32x2 %0, %1, %2;" : "=l"(d) : "l"(a), "l"(b));
    return d;
}
__device__ __forceinline__ ull PACK2(float a, float b) {
    union { ull u; float2 f; } x;
    x.f = make_float2(a, b);
    return x.u;
}
__device__ __forceinline__ float2 UNPK(ull a) {
    union { ull u; float2 f; } x;
    x.u = a;
    return x.f;
}
__device__ __forceinline__ float SIG(float v) {
    return 1.f / (1.f + __expf(-v));
}

// G=1 single-chain 50-dot, k-pairs packed in f32x2.
// 12 LDS.128 + 1 LDS.64 + 25 fma.f32x2; TWO accumulator chains (register-lean).
__device__ __forceinline__ float dot50(const float* __restrict__ a,
                                       const ull* __restrict__ w) {
    ull a0 = 0, a1 = 0;
#pragma unroll
    for (int j = 0; j < 6; j++) {
        ulonglong2 v0 = *(const ulonglong2*)(a + 8 * j);
        ulonglong2 v1 = *(const ulonglong2*)(a + 8 * j + 4);
        a0 = FMA2(w[4 * j + 0], v0.x, a0);
        a1 = FMA2(w[4 * j + 1], v0.y, a1);
        a0 = FMA2(w[4 * j + 2], v1.x, a0);
        a1 = FMA2(w[4 * j + 3], v1.y, a1);
    }
    a0 = FMA2(w[24], *(const ull*)(a + 48), a0);
    float2 s = UNPK(ADD2(a0, a1));
    return s.x + s.y;
}

// ---------------------------------------------------------------------------
// k01: merged constant folding (k0 role, 32 blocks) + vocab tables (k1 role,
// 7500 blocks x 4 vocab rows). Reg-capped for occupancy.
// ---------------------------------------------------------------------------
__global__ void __launch_bounds__(160, 6)
k01(const float* __restrict__ C_embed, const float* __restrict__ C_w,
    const float* __restrict__ S1w, const float* __restrict__ S2w,
    const float* __restrict__ WW, const float* __restrict__ hT,
    const float* __restrict__ S2, const float* __restrict__ prio_a,
    const float* __restrict__ W_embed, const float* __restrict__ embed_r,
    const float* __restrict__ V_embed, const float* __restrict__ beta,
    const float* __restrict__ Wrs1, const float* __restrict__ bs1) {
    __shared__ float sm[VR * DN + VR * RN];
    __shared__ float k0sm[2 * RN + 2 * RWN];
    int t = threadIdx.x;

    if (blockIdx.x >= K1BLOCKS) {
        // ---------------- k0 role ----------------
        float* cvs = k0sm;
        float* u   = k0sm + RN;
        float* cw  = k0sm + 2 * RN;
        float* uw  = k0sm + 2 * RN + RWN;
        if (t < RN) {
            float s = 0.f;
#pragma unroll
            for (int c = 0; c < CN; c++) s += C_embed[c * RN + t];
            cvs[t] = s;
            float su = 0.f;
#pragma unroll
            for (int s2 = 0; s2 < SN; s2++) su += hT[s2] * S2[s2 * RN + t];
            u[t] = su;
        }
        if (t < RWN) {
            float s = 0.f;
#pragma unroll
            for (int c = 0; c < CN; c++) s += C_w[c * RWN + t];
            cw[t] = s;
            float su = 0.f;
#pragma unroll
            for (int s2 = 0; s2 < SN; s2++) su += hT[s2] * S2w[s2 * RWN + t];
            uw[t] = su;
        }
        __syncthreads();

        const int N_WLD = SN * SN;      // 2500
        const int N_S2C = RN * SN;      // 7500
        const int N_SCF = PHW * CN;     // 4000
        const int TOT = N_WLD + N_S2C + N_SCF;
        int bid = blockIdx.x - K1BLOCKS;
        int stride = K0BLOCKS * 160;
        for (int g = bid * 160 + t; g < TOT; g += stride) {
            int i = g;
            if (i < N_WLD) {
                int s = i / SN, tt = i % SN;
                float acc = WW[i];
#pragma unroll
                for (int r = 0; r < RWN; r++)
                    acc += S1w[s * RWN + r] * cw[r] * S2w[tt * RWN + r];
                g_wild[i] = acc;
                continue;
            }
            i -= N_WLD;
            if (i < N_S2C) {
                int r = i / SN, tt = i % SN;
                g_S2cT[i] = S2[tt * RN + r] * cvs[r];
                continue;
            }
            i -= N_S2C;
            {
                int k = i / CN, c = i % CN;
                float v;
                if (k < RN) {
                    v = C_embed[c * RN + k] * u[k];
                } else {
                    int s = k - RN;
                    float acc = 0.f;
#pragma unroll
                    for (int r = 0; r < RWN; r++)
                        acc += S1w[s * RWN + r] * uw[r] * C_w[c * RWN + r];
                    v = acc;
                }
                g_SCf[i] = v * prio_a[c];
            }
        }
        return;
    }

    // ---------------- k1 role (VR=4) ----------------
    float* w4 = sm;
    float (*q4)[RN] = (float (*)[RN])(sm + VR * DN);
    int v0 = blockIdx.x * VR;

    for (int i = t; i < VR * DN; i += 160)
        w4[i] = W_embed[v0 * DN + i];
    __syncthreads();

    if (t < RN) {
        float cv = 0.f;
#pragma unroll
        for (int c = 0; c < CN; c++) cv += C_embed[c * RN + t];

        float a0 = 0.f, a1 = 0.f, a2 = 0.f, a3 = 0.f;
#pragma unroll 4
        for (int d = 0; d < DN; d++) {
            float e = embed_r[d * RN + t];
            a0 += e * w4[0 * DN + d];
            a1 += e * w4[1 * DN + d];
            a2 += e * w4[2 * DN + d];
            a3 += e * w4[3 * DN + d];
        }
        float b = beta[t];
        float acc[VR] = {a0, a1, a2, a3};
#pragma unroll
        for (int r = 0; r < VR; r++) {
            float th;
            asm("tanh.approx.f32 %0, %1;" : "=f"(th) : "f"(acc[r]));
            float tv = V_embed[(v0 + r) * RN + t] * b + th * (1.f - b);
            g_Tv[(v0 + r) * RN + t] = tv;
            q4[r][t] = tv * cv;
        }
    }
    __syncthreads();

    if (t < SN) {
        float a0 = 0.f, a1 = 0.f, a2 = 0.f, a3 = 0.f;
#pragma unroll 2
        for (int d = 0; d < RN; d++) {
            float wv = Wrs1[d * SN + t];
            a0 += wv * q4[0][d];
            a1 += wv * q4[1][d];
            a2 += wv * q4[2][d];
            a3 += wv * q4[3][d];
        }
        float bb = bs1[t];
        g_Trw[(v0 + 0) * SN + t] = bb + a0;
        g_Trw[(v0 + 1) * SN + t] = bb + a1;
        g_Trw[(v0 + 2) * SN + t] = bb + a2;
        g_Trw[(v0 + 3) * SN + t] = bb + a3;
    }
}

// ---------------------------------------------------------------------------
// k2: sequential recurrence, score-deferred, max-eligibility config.
// 256 CTAs x 448 threads (14 warps), 1 chain/CTA, G=1 (25 packed ull = 50
// weight regs, ~66 total) -> __launch_bounds__(448, 2) = 72-reg cap,
// 2 CTAs/SM, 28 resident warps, 14 working warps per interval.
//
//   warps 0-6 (t<200 active): phase-1. t<150: p[t] = (h@S1)[t]*Tv[tok];
//     t in [150,200): gate gz. Interval B: p-store to g_PH + Tv/Trw prefetch.
//   warps 7-13 (i=t-224): phase-2. Output o=i>>2, chunk q=i&3 (q<3: S2cT
//     over p-window; q=3: wild over live h). ALL lanes (incl. i>=200, which
//     carry zero weights and a valid default window) execute the dot +
//     shfl_xor(1,2) so shuffle masks stay full — the R15 hang was a
//     partial-warp full-mask shuffle in warp 13. Lane q==0 && i<200 blends
//     the gate and writes h (double-buffered).
//     Interval A: i<50 stores h_l to g_PH; i==200 loads next token.
//
// Shared: h0 @0, h1 @WIN, p0/p1/p2 @(2..4)*WIN. 2 barriers/step.
// ---------------------------------------------------------------------------
__global__ void __launch_bounds__(448, 2)
k2_recur(const int* __restrict__ tokens,
         const float* __restrict__ S1,
         const float* __restrict__ Wss1,
         const float* __restrict__ h0) {
    __shared__ float act[5 * WIN];
    __shared__ float gz[SN];
    __shared__ int s_ntok;

    int t = threadIdx.x;
    int b = blockIdx.x;
    int tb = b * LN;
    long rb = (long)b * LN;          // PH row base

    ull w[25];
#pragma unroll
    for (int j = 0; j < 25; j++) w[j] = 0ull;

    const bool isP1 = (t < 224);

    // phase-1 role
    int fam = 3;               // 0=p, 1=gate, 3=inactive
    int p1w = 0;
    // phase-2 role
    int o2 = 0;
    bool winIsH = false, p2w = false;
    int winOff = 2 * WIN;

    if (isP1) {
        if (t < 150) {
            fam = 0;
            p1w = (2 + t / 50) * WIN + (t % 50);
#pragma unroll
            for (int j = 0; j < 25; j++)
                w[j] = PACK2(S1[(2 * j) * RN + t], S1[(2 * j + 1) * RN + t]);
        } else if (t < 200) {
            fam = 1;
            int col = t - 150;
#pragma unroll
            for (int j = 0; j < 25; j++)
                w[j] = PACK2(Wss1[(2 * j) * SN + col],
                             Wss1[(2 * j + 1) * SN + col]);
        }
    } else {
        int i = t - 224;
        if (i < 200) {
            int q = i & 3;
            o2 = i >> 2;
            p2w = (q == 0);
            if (q < 3) {
                const float* P = g_S2cT + q * 50 * SN;
                winOff = (2 + q) * WIN;
#pragma unroll
                for (int j = 0; j < 25; j++)
                    w[j] = PACK2(P[(2 * j) * SN + o2],
                                 P[(2 * j + 1) * SN + o2]);
            } else {
                winIsH = true;
#pragma unroll
                for (int j = 0; j < 25; j++)
                    w[j] = PACK2(g_wild[(2 * j) * SN + o2],
                                 g_wild[(2 * j + 1) * SN + o2]);
            }
        }
        // i >= 200: zero weights, winOff = 2*WIN (valid reads), p2w = false
    }

    // ---- init: state + prime step-0 gathers ----
    if (t < SN) act[t] = h0[t];
    float tvA = 0.f, trA = 0.f;
    if (fam == 0) {
        tvA = g_Tv[tokens[tb] * RN + t];
    } else if (fam == 1) {
        trA = g_Trw[tokens[tb] * SN + (t - 150)];
    }
    __syncthreads();

    for (int l = 0; l < LN; l++) {
        int hc = (l & 1) ? WIN : 0;
        float pxv = 0.f;                 // p value kept for the gmem store

        // -------- interval A: phase-1 compute | h-store + token preload -----
        if (isP1) {
            if (fam != 3) {
                float ov = dot50(act + hc, w);
                if (fam == 0) {
                    pxv = ov * tvA;
                    act[p1w] = pxv;
                } else {
                    gz[t - 150] = SIG(ov + trA);
                }
            }
        } else {
            int i = t - 224;
            if (i < 50) {
                g_PH[(rb + l) * PHW + 150 + i] = act[hc + i];
            } else if (i == 200) {
                int nl = (l + 1 < LN) ? l + 1 : l;
                s_ntok = tokens[tb + nl];
            }
        }
        __syncthreads();

        // -------- interval B: phase-2 compute | p-store + prefetch ----------
        if (isP1) {
            if (fam == 0) {
                g_PH[(rb + l) * PHW + t] = pxv;
                tvA = g_Tv[s_ntok * RN + t];
            } else if (fam == 1) {
                trA = g_Trw[s_ntok * SN + (t - 150)];
            }
        } else {
            // ALL lanes of warps 7-13 execute (full-mask shuffles are safe);
            // lanes with i>=200 compute a zero dot into nothing.
            int aw2 = winIsH ? hc : winOff;
            float sx = dot50(act + aw2, w);

            sx += __shfl_xor_sync(0xffffffffu, sx, 1);
            sx += __shfl_xor_sync(0xffffffffu, sx, 2);

            if (p2w) {
                int hn = WIN - hc;
                float z = gz[o2];
                float hx = act[hc + o2];
                act[hn + o2] = z * sx + (1.f - z) * hx;
            }
        }
        __syncthreads();
    }
}

// ---------------------------------------------------------------------------
// k3: deferred scores. out[row][c] = [p|h](row) @ SCf + prio_b.
// 512 blocks x 256 threads, one row per thread; SCf broadcast from shared.
// ---------------------------------------------------------------------------
__global__ void __launch_bounds__(256)
k3_score(const float* __restrict__ prio_b, float* __restrict__ out) {
    __shared__ __align__(16) float sc[PHW * CN];
    int t = threadIdx.x;
    for (int i = t; i < PHW * CN; i += 256) sc[i] = g_SCf[i];
    __syncthreads();

    long row = (long)blockIdx.x * 256 + t;
    const float* ph = g_PH + row * PHW;

    ull acc[10];
#pragma unroll
    for (int c = 0; c < 10; c++) acc[c] = 0ull;

#pragma unroll 4
    for (int k = 0; k < PHW; k += 4) {
        float4 v = *(const float4*)(ph + k);
        const ull* s0 = (const ull*)(sc + (k + 0) * CN);
        const ull* s1 = (const ull*)(sc + (k + 1) * CN);
        const ull* s2 = (const ull*)(sc + (k + 2) * CN);
        const ull* s3 = (const ull*)(sc + (k + 3) * CN);
        ull v0 = PACK2(v.x, v.x), v1 = PACK2(v.y, v.y);
        ull v2 = PACK2(v.z, v.z), v3 = PACK2(v.w, v.w);
#pragma unroll
        for (int c = 0; c < 10; c++) {
            acc[c] = FMA2(s0[c], v0, acc[c]);
            acc[c] = FMA2(s1[c], v1, acc[c]);
            acc[c] = FMA2(s2[c], v2, acc[c]);
            acc[c] = FMA2(s3[c], v3, acc[c]);
        }
    }

    float* o = out + row * CN;
#pragma unroll
    for (int c = 0; c < 10; c++) {
        float2 a = UNPK(acc[c]);
        float2 pb = *(const float2*)(prio_b + 2 * c);
        *(float2*)(o + 2 * c) = make_float2(a.x + pb.x, a.y + pb.y);
    }
}

// ---------------------------------------------------------------------------
// Launch. Inputs (metadata order): tokens, W_embed, embed_r, V_embed,
// C_embed, S1, S2, S1_w, S2_w, C_w, WW, h0, hT, beta_vec, Wss1, Wrs1, bs1,
// prio_a, prio_b
// ---------------------------------------------------------------------------
extern "C" void kernel_launch(void* const* d_in, const int* in_sizes, int n_in,
                              void* d_out, int out_size) {
    const int*   tokens  = (const int*)  d_in[0];
    const float* W_embed = (const float*)d_in[1];
    const float* embed_r = (const float*)d_in[2];
    const float* V_embed = (const float*)d_in[3];
    const float* C_embed = (const float*)d_in[4];
    const float* S1      = (const float*)d_in[5];
    const float* S2      = (const float*)d_in[6];
    const float* S1_w    = (const float*)d_in[7];
    const float* S2_w    = (const float*)d_in[8];
    const float* C_w     = (const float*)d_in[9];
    const float* WW      = (const float*)d_in[10];
    const float* h0      = (const float*)d_in[11];
    const float* hT      = (const float*)d_in[12];
    const float* beta    = (const float*)d_in[13];
    const float* Wss1    = (const float*)d_in[14];
    const float* Wrs1    = (const float*)d_in[15];
    const float* bs1     = (const float*)d_in[16];
    const float* prio_a  = (const float*)d_in[17];
    const float* prio_b  = (const float*)d_in[18];
    float* out = (float*)d_out;

    k01<<<K1BLOCKS + K0BLOCKS, 160>>>(C_embed, C_w, S1_w, S2_w, WW, hT, S2,
                                      prio_a, W_embed, embed_r, V_embed, beta,
                                      Wrs1, bs1);
    k2_recur<<<BN, 448>>>(tokens, S1, Wss1, h0);
    k3_score<<<(BN * LN) / 256, 256>>>(prio_b, out);
}

// round 17
// speedup vs baseline: 1.5713x; 1.0449x over previous
#include <cuda_runtime.h>
#include <math.h>

#define VOCABN 30000
#define DN 100
#define RN 150
#define RWN 50
#define SN 50
#define CN 20
#define BN 256
#define LN 512
#define VR 8                      // vocab rows per k1-role block
#define K1BLOCKS (VOCABN / VR)    // 3750
#define K0BLOCKS 32
#define WIN 68                    // k2 shared window stride
#define PHW 200                   // per-(b,l) row: p[0:150] | h[150:200]

typedef unsigned long long ull;

// ---- folded constants / tables / deferred-score buffer (static device) ----
__device__ float g_Tv[VOCABN * RN];    // blended V embedding per vocab id
__device__ float g_Trw[VOCABN * SN];   // (Tv*Cvs)@Wrs1 + bs1 per vocab id
__device__ float g_wild[SN * SN];      // [s][t]
__device__ float g_S2cT[RN * SN];      // S2[t][r]*Cvs[r], stored [r][t]
__device__ float g_SCf[PHW * CN];      // [k][c] score matrix (prio_a folded)
__device__ float g_PH[(size_t)BN * LN * PHW];  // p|h per (b,l)  (~105 MB)

// ---- packed f32x2 helpers ----
__device__ __forceinline__ ull FMA2(ull a, ull b, ull c) {
    ull d;
    asm("fma.rn.f32x2 %0, %1, %2, %3;" : "=l"(d) : "l"(a), "l"(b), "l"(c));
    return d;
}
__device__ __forceinline__ ull ADD2(ull a, ull b) {
    ull d;
    asm("add.rn.f32x2 %0, %1, %2;" : "=l"(d) : "l"(a), "l"(b));
    return d;
}
__device__ __forceinline__ ull PACK2(float a, float b) {
    union { ull u; float2 f; } x;
    x.f = make_float2(a, b);
    return x.u;
}
__device__ __forceinline__ float2 UNPK(ull a) {
    union { ull u; float2 f; } x;
    x.u = a;
    return x.f;
}
__device__ __forceinline__ float SIG(float v) {
    return 1.f / (1.f + __expf(-v));
}

// G=1 single-chain 50-dot, k-pairs packed in f32x2.
// 12 LDS.128 + 1 LDS.64 + 25 fma.f32x2; TWO accumulator chains (register-lean).
__device__ __forceinline__ float dot50(const float* __restrict__ a,
                                       const ull* __restrict__ w) {
    ull a0 = 0, a1 = 0;
#pragma unroll
    for (int j = 0; j < 6; j++) {
        ulonglong2 v0 = *(const ulonglong2*)(a + 8 * j);
        ulonglong2 v1 = *(const ulonglong2*)(a + 8 * j + 4);
        a0 = FMA2(w[4 * j + 0], v0.x, a0);
        a1 = FMA2(w[4 * j + 1], v0.y, a1);
        a0 = FMA2(w[4 * j + 2], v1.x, a0);
        a1 = FMA2(w[4 * j + 3], v1.y, a1);
    }
    a0 = FMA2(w[24], *(const ull*)(a + 48), a0);
    float2 s = UNPK(ADD2(a0, a1));
    return s.x + s.y;
}

// ---------------------------------------------------------------------------
// k01: merged constant folding (k0 role, 32 blocks) + vocab tables (k1 role,
// 3750 blocks x 8 vocab rows).
// k1 role rebuilt for CROSSBAR efficiency: weights interleaved [d][r] so one
// broadcast LDS.128 (1 wavefront) serves 4 rows; row-pairs packed into
// fma.rn.f32x2. Same for phase-B via qT[d][r].
// ---------------------------------------------------------------------------
__global__ void __launch_bounds__(160, 6)
k01(const float* __restrict__ C_embed, const float* __restrict__ C_w,
    const float* __restrict__ S1w, const float* __restrict__ S2w,
    const float* __restrict__ WW, const float* __restrict__ hT,
    const float* __restrict__ S2, const float* __restrict__ prio_a,
    const float* __restrict__ W_embed, const float* __restrict__ embed_r,
    const float* __restrict__ V_embed, const float* __restrict__ beta,
    const float* __restrict__ Wrs1, const float* __restrict__ bs1) {
    __shared__ __align__(16) float wT[VR * DN];   // [d][r] interleaved
    __shared__ __align__(16) float qT[VR * RN];   // [d][r] interleaved
    __shared__ float k0sm[2 * RN + 2 * RWN];
    int t = threadIdx.x;

    if (blockIdx.x >= K1BLOCKS) {
        // ---------------- k0 role (unchanged) ----------------
        float* cvs = k0sm;
        float* u   = k0sm + RN;
        float* cw  = k0sm + 2 * RN;
        float* uw  = k0sm + 2 * RN + RWN;
        if (t < RN) {
            float s = 0.f;
#pragma unroll
            for (int c = 0; c < CN; c++) s += C_embed[c * RN + t];
            cvs[t] = s;
            float su = 0.f;
#pragma unroll
            for (int s2 = 0; s2 < SN; s2++) su += hT[s2] * S2[s2 * RN + t];
            u[t] = su;
        }
        if (t < RWN) {
            float s = 0.f;
#pragma unroll
            for (int c = 0; c < CN; c++) s += C_w[c * RWN + t];
            cw[t] = s;
            float su = 0.f;
#pragma unroll
            for (int s2 = 0; s2 < SN; s2++) su += hT[s2] * S2w[s2 * RWN + t];
            uw[t] = su;
        }
        __syncthreads();

        const int N_WLD = SN * SN;      // 2500
        const int N_S2C = RN * SN;      // 7500
        const int N_SCF = PHW * CN;     // 4000
        const int TOT = N_WLD + N_S2C + N_SCF;
        int bid = blockIdx.x - K1BLOCKS;
        int stride = K0BLOCKS * 160;
        for (int g = bid * 160 + t; g < TOT; g += stride) {
            int i = g;
            if (i < N_WLD) {
                int s = i / SN, tt = i % SN;
                float acc = WW[i];
#pragma unroll
                for (int r = 0; r < RWN; r++)
                    acc += S1w[s * RWN + r] * cw[r] * S2w[tt * RWN + r];
                g_wild[i] = acc;
                continue;
            }
            i -= N_WLD;
            if (i < N_S2C) {
                int r = i / SN, tt = i % SN;
                g_S2cT[i] = S2[tt * RN + r] * cvs[r];
                continue;
            }
            i -= N_S2C;
            {
                int k = i / CN, c = i % CN;
                float v;
                if (k < RN) {
                    v = C_embed[c * RN + k] * u[k];
                } else {
                    int s = k - RN;
                    float acc = 0.f;
#pragma unroll
                    for (int r = 0; r < RWN; r++)
                        acc += S1w[s * RWN + r] * uw[r] * C_w[c * RWN + r];
                    v = acc;
                }
                g_SCf[i] = v * prio_a[c];
            }
        }
        return;
    }

    // ---------------- k1 role (VR=8, interleaved broadcasts) ----------------
    int v0 = blockIdx.x * VR;

    // wT[d*8 + r] = W_embed[v0+r][d]
    for (int i = t; i < VR * DN; i += 160)
        wT[i] = W_embed[(v0 + (i & (VR - 1))) * DN + (i >> 3)];
    __syncthreads();

    if (t < RN) {
        float cv = 0.f;
#pragma unroll
        for (int c = 0; c < CN; c++) cv += C_embed[c * RN + t];

        // acc pairs: acc0=(r0,r1) acc1=(r2,r3) acc2=(r4,r5) acc3=(r6,r7)
        ull ac0 = 0, ac1 = 0, ac2 = 0, ac3 = 0;
        const ulonglong2* wT2 = (const ulonglong2*)wT;
#pragma unroll 4
        for (int d = 0; d < DN; d++) {
            float e = embed_r[d * RN + t];
            ull ep = PACK2(e, e);
            ulonglong2 wa = wT2[2 * d];       // rows 0..3 (broadcast, 1 wf)
            ulonglong2 wb = wT2[2 * d + 1];   // rows 4..7
            ac0 = FMA2(wa.x, ep, ac0);
            ac1 = FMA2(wa.y, ep, ac1);
            ac2 = FMA2(wb.x, ep, ac2);
            ac3 = FMA2(wb.y, ep, ac3);
        }

        float accv[VR];
        { float2 v = UNPK(ac0); accv[0] = v.x; accv[1] = v.y; }
        { float2 v = UNPK(ac1); accv[2] = v.x; accv[3] = v.y; }
        { float2 v = UNPK(ac2); accv[4] = v.x; accv[5] = v.y; }
        { float2 v = UNPK(ac3); accv[6] = v.x; accv[7] = v.y; }

        float b = beta[t];
#pragma unroll
        for (int r = 0; r < VR; r++) {
            float th;
            asm("tanh.approx.f32 %0, %1;" : "=f"(th) : "f"(accv[r]));
            float tv = V_embed[(v0 + r) * RN + t] * b + th * (1.f - b);
            g_Tv[(v0 + r) * RN + t] = tv;
            qT[t * VR + r] = tv * cv;        // [d][r] interleaved
        }
    }
    __syncthreads();

    if (t < SN) {
        ull ac0 = 0, ac1 = 0, ac2 = 0, ac3 = 0;
        const ulonglong2* qT2 = (const ulonglong2*)qT;
#pragma unroll 2
        for (int d = 0; d < RN; d++) {
            float wv = Wrs1[d * SN + t];
            ull wp = PACK2(wv, wv);
            ulonglong2 qa = qT2[2 * d];       // rows 0..3 (broadcast)
            ulonglong2 qb = qT2[2 * d + 1];   // rows 4..7
            ac0 = FMA2(qa.x, wp, ac0);
            ac1 = FMA2(qa.y, wp, ac1);
            ac2 = FMA2(qb.x, wp, ac2);
            ac3 = FMA2(qb.y, wp, ac3);
        }
        float bb = bs1[t];
        float2 v;
        v = UNPK(ac0);
        g_Trw[(v0 + 0) * SN + t] = bb + v.x;
        g_Trw[(v0 + 1) * SN + t] = bb + v.y;
        v = UNPK(ac1);
        g_Trw[(v0 + 2) * SN + t] = bb + v.x;
        g_Trw[(v0 + 3) * SN + t] = bb + v.y;
        v = UNPK(ac2);
        g_Trw[(v0 + 4) * SN + t] = bb + v.x;
        g_Trw[(v0 + 5) * SN + t] = bb + v.y;
        v = UNPK(ac3);
        g_Trw[(v0 + 6) * SN + t] = bb + v.x;
        g_Trw[(v0 + 7) * SN + t] = bb + v.y;
    }
}

// ---------------------------------------------------------------------------
// k2: sequential recurrence, score-deferred (UNCHANGED from R16 — passing).
// 256 CTAs x 448 threads, 1 chain/CTA, G=1, __launch_bounds__(448,2).
// ---------------------------------------------------------------------------
__global__ void __launch_bounds__(448, 2)
k2_recur(const int* __restrict__ tokens,
         const float* __restrict__ S1,
         const float* __restrict__ Wss1,
         const float* __restrict__ h0) {
    __shared__ float act[5 * WIN];
    __shared__ float gz[SN];
    __shared__ int s_ntok;

    int t = threadIdx.x;
    int b = blockIdx.x;
    int tb = b * LN;
    long rb = (long)b * LN;          // PH row base

    ull w[25];
#pragma unroll
    for (int j = 0; j < 25; j++) w[j] = 0ull;

    const bool isP1 = (t < 224);

    // phase-1 role
    int fam = 3;               // 0=p, 1=gate, 3=inactive
    int p1w = 0;
    // phase-2 role
    int o2 = 0;
    bool winIsH = false, p2w = false;
    int winOff = 2 * WIN;

    if (isP1) {
        if (t < 150) {
            fam = 0;
            p1w = (2 + t / 50) * WIN + (t % 50);
#pragma unroll
            for (int j = 0; j < 25; j++)
                w[j] = PACK2(S1[(2 * j) * RN + t], S1[(2 * j + 1) * RN + t]);
        } else if (t < 200) {
            fam = 1;
            int col = t - 150;
#pragma unroll
            for (int j = 0; j < 25; j++)
                w[j] = PACK2(Wss1[(2 * j) * SN + col],
                             Wss1[(2 * j + 1) * SN + col]);
        }
    } else {
        int i = t - 224;
        if (i < 200) {
            int q = i & 3;
            o2 = i >> 2;
            p2w = (q == 0);
            if (q < 3) {
                const float* P = g_S2cT + q * 50 * SN;
                winOff = (2 + q) * WIN;
#pragma unroll
                for (int j = 0; j < 25; j++)
                    w[j] = PACK2(P[(2 * j) * SN + o2],
                                 P[(2 * j + 1) * SN + o2]);
            } else {
                winIsH = true;
#pragma unroll
                for (int j = 0; j < 25; j++)
                    w[j] = PACK2(g_wild[(2 * j) * SN + o2],
                                 g_wild[(2 * j + 1) * SN + o2]);
            }
        }
        // i >= 200: zero weights, winOff = 2*WIN (valid reads), p2w = false
    }

    // ---- init: state + prime step-0 gathers ----
    if (t < SN) act[t] = h0[t];
    float tvA = 0.f, trA = 0.f;
    if (fam == 0) {
        tvA = g_Tv[tokens[tb] * RN + t];
    } else if (fam == 1) {
        trA = g_Trw[tokens[tb] * SN + (t - 150)];
    }
    __syncthreads();

    for (int l = 0; l < LN; l++) {
        int hc = (l & 1) ? WIN : 0;
        float pxv = 0.f;                 // p value kept for the gmem store

        // -------- interval A: phase-1 compute | h-store + token preload -----
        if (isP1) {
            if (fam != 3) {
                float ov = dot50(act + hc, w);
                if (fam == 0) {
                    pxv = ov * tvA;
                    act[p1w] = pxv;
                } else {
                    gz[t - 150] = SIG(ov + trA);
                }
            }
        } else {
            int i = t - 224;
            if (i < 50) {
                g_PH[(rb + l) * PHW + 150 + i] = act[hc + i];
            } else if (i == 200) {
                int nl = (l + 1 < LN) ? l + 1 : l;
                s_ntok = tokens[tb + nl];
            }
        }
        __syncthreads();

        // -------- interval B: phase-2 compute | p-store + prefetch ----------
        if (isP1) {
            if (fam == 0) {
                g_PH[(rb + l) * PHW + t] = pxv;
                tvA = g_Tv[s_ntok * RN + t];
            } else if (fam == 1) {
                trA = g_Trw[s_ntok * SN + (t - 150)];
            }
        } else {
            // ALL lanes of warps 7-13 execute (full-mask shuffles are safe);
            // lanes with i>=200 compute a zero dot into nothing.
            int aw2 = winIsH ? hc : winOff;
            float sx = dot50(act + aw2, w);

            sx += __shfl_xor_sync(0xffffffffu, sx, 1);
            sx += __shfl_xor_sync(0xffffffffu, sx, 2);

            if (p2w) {
                int hn = WIN - hc;
                float z = gz[o2];
                float hx = act[hc + o2];
                act[hn + o2] = z * sx + (1.f - z) * hx;
            }
        }
        __syncthreads();
    }
}

// ---------------------------------------------------------------------------
// k3: deferred scores. out[row][c] = [p|h](row) @ SCf + prio_b.
// 512 blocks x 256 threads, one row per thread; SCf broadcast from shared.
// ---------------------------------------------------------------------------
__global__ void __launch_bounds__(256)
k3_score(const float* __restrict__ prio_b, float* __restrict__ out) {
    __shared__ __align__(16) float sc[PHW * CN];
    int t = threadIdx.x;
    for (int i = t; i < PHW * CN; i += 256) sc[i] = g_SCf[i];
    __syncthreads();

    long row = (long)blockIdx.x * 256 + t;
    const float* ph = g_PH + row * PHW;

    ull acc[10];
#pragma unroll
    for (int c = 0; c < 10; c++) acc[c] = 0ull;

#pragma unroll 4
    for (int k = 0; k < PHW; k += 4) {
        float4 v = *(const float4*)(ph + k);
        const ull* s0 = (const ull*)(sc + (k + 0) * CN);
        const ull* s1 = (const ull*)(sc + (k + 1) * CN);
        const ull* s2 = (const ull*)(sc + (k + 2) * CN);
        const ull* s3 = (const ull*)(sc + (k + 3) * CN);
        ull v0 = PACK2(v.x, v.x), v1 = PACK2(v.y, v.y);
        ull v2 = PACK2(v.z, v.z), v3 = PACK2(v.w, v.w);
#pragma unroll
        for (int c = 0; c < 10; c++) {
            acc[c] = FMA2(s0[c], v0, acc[c]);
            acc[c] = FMA2(s1[c], v1, acc[c]);
            acc[c] = FMA2(s2[c], v2, acc[c]);
            acc[c] = FMA2(s3[c], v3, acc[c]);
        }
    }

    float* o = out + row * CN;
#pragma unroll
    for (int c = 0; c < 10; c++) {
        float2 a = UNPK(acc[c]);
        float2 pb = *(const float2*)(prio_b + 2 * c);
        *(float2*)(o + 2 * c) = make_float2(a.x + pb.x, a.y + pb.y);
    }
}

// ---------------------------------------------------------------------------
// Launch. Inputs (metadata order): tokens, W_embed, embed_r, V_embed,
// C_embed, S1, S2, S1_w, S2_w, C_w, WW, h0, hT, beta_vec, Wss1, Wrs1, bs1,
// prio_a, prio_b
// ---------------------------------------------------------------------------
extern "C" void kernel_launch(void* const* d_in, const int* in_sizes, int n_in,
                              void* d_out, int out_size) {
    const int*   tokens  = (const int*)  d_in[0];
    const float* W_embed = (const float*)d_in[1];
    const float* embed_r = (const float*)d_in[2];
    const float* V_embed = (const float*)d_in[3];
    const float* C_embed = (const float*)d_in[4];
    const float* S1      = (const float*)d_in[5];
    const float* S2      = (const float*)d_in[6];
    const float* S1_w    = (const float*)d_in[7];
    const float* S2_w    = (const float*)d_in[8];
    const float* C_w     = (const float*)d_in[9];
    const float* WW      = (const float*)d_in[10];
    const float* h0      = (const float*)d_in[11];
    const float* hT      = (const float*)d_in[12];
    const float* beta    = (const float*)d_in[13];
    const float* Wss1    = (const float*)d_in[14];
    const float* Wrs1    = (const float*)d_in[15];
    const float* bs1     = (const float*)d_in[16];
    const float* prio_a  = (const float*)d_in[17];
    const float* prio_b  = (const float*)d_in[18];
    float* out = (float*)d_out;

    k01<<<K1BLOCKS + K0BLOCKS, 160>>>(C_embed, C_w, S1_w, S2_w, WW, hT, S2,
                                      prio_a, W_embed, embed_r, V_embed, beta,
                                      Wrs1, bs1);
    k2_recur<<<BN, 448>>>(tokens, S1, Wss1, h0);
    k3_score<<<(BN * LN) / 256, 256>>>(prio_b, out);
}